// round 4
// baseline (speedup 1.0000x reference)
#include <cuda_runtime.h>
#include <cstdint>
#include <cstddef>

#define TT 256
#define BB 64
#define HH 512
#define G6 3072
#define G5 2560
#define LAYER_W_STRIDE (512*3072 + 512*2560)   /* 2883584 */
#define WHH_OFF (512*3072)                      /* 1572864 */
#define NCTA 128

// ---------------- device scratch (static, no runtime alloc) ----------------
__device__ float g_x [(size_t)TT*BB*HH];          // layer input  [t][b][k]
__device__ float g_y [(size_t)TT*BB*HH];          // layer output [t][b][k]
__device__ float g_xi[(size_t)TT*BB*G6];          // xi [t][b][g]
__device__ float g_h0[BB*HH];
__device__ float g_h1[BB*HH];
__device__ float g_wt[(size_t)4*G5*HH];           // W_hh packed [l][hid][gate][k]
__device__ unsigned g_bar[2];                     // [0]=count, [1]=epoch

// ---------------- f32x2 packed FMA (sm_100+) ----------------
__device__ __forceinline__ float2 ffma2(float2 a, float2 b, float2 c) {
    union U { float2 f; unsigned long long u; };
    U A, B, C, D;
    A.f = a; B.f = b; C.f = c;
    asm("fma.rn.f32x2 %0, %1, %2, %3;" : "=l"(D.u) : "l"(A.u), "l"(B.u), "l"(C.u));
    return D.f;
}

__device__ __forceinline__ float sigmoidf_(float x) {
    return 1.0f / (1.0f + __expf(-x));
}

// ---------------- prep: transpose (B,T,H)->(T,B,H) and mask ----------------
__global__ void prep_kernel(const float* __restrict__ in, const int* __restrict__ len) {
    int idx = blockIdx.x * blockDim.x + threadIdx.x;   // float4 elements
    if (idx >= TT*BB*HH/4) return;
    int k4 = idx & 127;
    int b  = (idx >> 7) & 63;
    int t  = idx >> 13;
    float4 v = make_float4(0.f, 0.f, 0.f, 0.f);
    if (t < len[b])
        v = *(const float4*)(in + (size_t)(b*TT + t)*HH + k4*4);
    *(float4*)(g_x + (size_t)idx*4) = v;
}

// ---------------- pack W_hh[k][g*512+hid] -> wt[l][(hid*5+g)][k] ----------------
__global__ void packw_kernel(const float* __restrict__ weight) {
    int idx = blockIdx.x * blockDim.x + threadIdx.x;
    if (idx >= 4*HH*G5) return;
    int col = idx % G5;
    int k   = (idx / G5) % HH;
    int l   = idx / (G5*HH);
    int hid = col & 511, g = col >> 9;
    float v = weight[(size_t)l*LAYER_W_STRIDE + WHH_OFF + (size_t)k*G5 + col];
    g_wt[(size_t)l*(G5*HH) + (size_t)((hid*5 + g) << 9) + k] = v;
}

// ---------------- xi GEMM: (16384x512)x(512x3072), gathered A rows ----------------
__global__ __launch_bounds__(256, 2)
void gemm_xi_kernel(const float* __restrict__ X, const float* __restrict__ W,
                    float* __restrict__ XI, const int* __restrict__ len, int rev)
{
    __shared__ float As[8][128];
    __shared__ float Bs[8][128];
    __shared__ int   srow[128];
    int tid = threadIdx.x;
    int rowBase = blockIdx.x * 128;
    int colBase = blockIdx.y * 128;
    if (tid < 128) {
        int r = rowBase + tid;
        int t = r >> 6, b = r & 63;
        if (rev) { int L = len[b]; t = (t < L) ? (L - 1 - t) : t; }
        srow[tid] = t*BB + b;
    }
    __syncthreads();

    float2 acc[8][4];
    #pragma unroll
    for (int i = 0; i < 8; i++)
        #pragma unroll
        for (int j = 0; j < 4; j++) acc[i][j] = make_float2(0.f, 0.f);

    int am = tid >> 1, akq = (tid & 1) * 4;
    int bk = tid >> 5, bn  = (tid & 31) * 4;
    int ty8 = (tid >> 4) * 8, tx8 = (tid & 15) * 8;

    for (int k0 = 0; k0 < 512; k0 += 8) {
        float4 av = *(const float4*)(X + (size_t)srow[am]*HH + k0 + akq);
        float4 bv = *(const float4*)(W + (size_t)(k0 + bk)*G6 + colBase + bn);
        As[akq+0][am] = av.x; As[akq+1][am] = av.y;
        As[akq+2][am] = av.z; As[akq+3][am] = av.w;
        *(float4*)&Bs[bk][bn] = bv;
        __syncthreads();
        #pragma unroll
        for (int kk = 0; kk < 8; kk++) {
            float4 a0 = *(float4*)&As[kk][ty8];
            float4 a1 = *(float4*)&As[kk][ty8+4];
            float4 b0 = *(float4*)&Bs[kk][tx8];
            float4 b1 = *(float4*)&Bs[kk][tx8+4];
            float  ar[8] = {a0.x,a0.y,a0.z,a0.w,a1.x,a1.y,a1.z,a1.w};
            float2 br[4] = {make_float2(b0.x,b0.y), make_float2(b0.z,b0.w),
                            make_float2(b1.x,b1.y), make_float2(b1.z,b1.w)};
            #pragma unroll
            for (int i = 0; i < 8; i++) {
                float2 ad = make_float2(ar[i], ar[i]);
                #pragma unroll
                for (int jp = 0; jp < 4; jp++)
                    acc[i][jp] = ffma2(ad, br[jp], acc[i][jp]);
            }
        }
        __syncthreads();
    }

    #pragma unroll
    for (int i = 0; i < 8; i++) {
        float* out = XI + (size_t)(rowBase + ty8 + i)*G6 + colBase + tx8;
        *(float4*)(out)     = make_float4(acc[i][0].x, acc[i][0].y, acc[i][1].x, acc[i][1].y);
        *(float4*)(out + 4) = make_float4(acc[i][2].x, acc[i][2].y, acc[i][3].x, acc[i][3].y);
    }
}

// ---------------- persistent per-layer recurrence ----------------
// 128 CTAs (one per SM, all co-resident) x 256 threads.
// CTA owns 4 hidden units for all 256 steps. Weights live in smem for the
// whole layer; c lives in a register; h ping-pongs through global with a
// software grid barrier between steps.
__global__ __launch_bounds__(256)
void lstm_layer_kernel(const float* __restrict__ xi_base, // [T][B][G6]
                       const float* __restrict__ wt,      // packed layer W_hh
                       const float* __restrict__ bias,    // [G5]
                       const int*   __restrict__ len,
                       float* __restrict__ hbuf0,
                       float* __restrict__ hbuf1,
                       float* __restrict__ y,
                       int rev)
{
    __shared__ float sh_w[20*512];     // 40 KB: this CTA's 20 weight rows
    __shared__ float sh_h[64*68];      // 17 KB: 64-k chunk of h, pad-68 (conflict-free)

    int tid = threadIdx.x;
    int hl = tid >> 6, b = tid & 63;
    int hid0 = blockIdx.x * 4;
    int hid  = hid0 + hl;

    // one-time loads
    const float4* wsrc = (const float4*)(wt + (size_t)hid0 * 5 * 512);
    #pragma unroll
    for (int i = tid; i < 20*512/4; i += 256)
        ((float4*)sh_w)[i] = wsrc[i];

    float bval[5];
    #pragma unroll
    for (int g = 0; g < 5; g++) bval[g] = bias[g*512 + hid];
    int L = len[b];
    float c = 0.0f;

    const float* hin = hbuf0;
    float*       hout = hbuf1;

    int sb = tid >> 2;                 // staging batch row 0..63
    int sk = (tid & 3) * 16;           // staging k offset within 64-chunk

    __syncthreads();

    for (int s = 0; s < TT; s++) {
        const float* xi = xi_base + (size_t)s * BB * G6;

        float2 acc[5];
        #pragma unroll
        for (int g = 0; g < 5; g++) acc[g] = make_float2(0.f, 0.f);

        for (int k0 = 0; k0 < 512; k0 += 64) {
            // stage h chunk (bypass L1: h is produced by other SMs)
            const float4* hsrc = (const float4*)(hin + (size_t)sb*HH + k0 + sk);
            float4 v0 = __ldcg(hsrc + 0);
            float4 v1 = __ldcg(hsrc + 1);
            float4 v2 = __ldcg(hsrc + 2);
            float4 v3 = __ldcg(hsrc + 3);
            *(float4*)&sh_h[sb*68 + sk +  0] = v0;
            *(float4*)&sh_h[sb*68 + sk +  4] = v1;
            *(float4*)&sh_h[sb*68 + sk +  8] = v2;
            *(float4*)&sh_h[sb*68 + sk + 12] = v3;
            __syncthreads();
            #pragma unroll
            for (int kk = 0; kk < 64; kk += 4) {
                float4 hv = *(float4*)&sh_h[b*68 + kk];
                float2 h01 = make_float2(hv.x, hv.y);
                float2 h23 = make_float2(hv.z, hv.w);
                #pragma unroll
                for (int g = 0; g < 5; g++) {
                    float4 wv = *(float4*)&sh_w[(hl*5 + g)*512 + k0 + kk];
                    acc[g] = ffma2(h01, make_float2(wv.x, wv.y), acc[g]);
                    acc[g] = ffma2(h23, make_float2(wv.z, wv.w), acc[g]);
                }
            }
            __syncthreads();
        }

        float gv[5];
        #pragma unroll
        for (int g = 0; g < 5; g++)
            gv[g] = acc[g].x + acc[g].y
                  + xi[(size_t)b*G6 + g*512 + hid] + bval[g];

        float ig = sigmoidf_(gv[0]);
        float fg = sigmoidf_(gv[1]);
        float gc = tanhf(gv[2]);
        float og = sigmoidf_(gv[3]);
        float rg = sigmoidf_(gv[4]);
        float lin = xi[(size_t)b*G6 + 5*512 + hid];

        float cn, hn;
        if (s < L) {
            cn = fg*c + ig*gc;
            hn = rg*(og*tanhf(cn)) + (1.f - rg)*lin;
        } else {
            cn = 0.f; hn = 0.f;
        }
        c = cn;
        hout[b*HH + hid] = hn;
        int dst = rev ? ((s < L) ? (L - 1 - s) : s) : s;
        y[((size_t)dst*BB + b)*HH + hid] = hn;

        // ---- grid barrier (sense via monotonically increasing epoch) ----
        if (s != TT-1) {
            __threadfence();
            __syncthreads();
            if (tid == 0) {
                unsigned target = (unsigned)(s + 1);
                if (atomicAdd(&g_bar[0], 1u) == NCTA - 1) {
                    atomicExch(&g_bar[0], 0u);
                    __threadfence();
                    atomicAdd(&g_bar[1], 1u);
                }
                unsigned v;
                for (;;) {
                    asm volatile("ld.acquire.gpu.u32 %0, [%1];"
                                 : "=r"(v) : "l"(&g_bar[1]));
                    if (v >= target) break;
                    __nanosleep(64);
                }
            }
            __syncthreads();
        }

        // swap h buffers
        const float* tmp = hin; hin = hout; hout = (float*)tmp;
    }
}

// ---------------- final transpose (T,B,H)->(B,T,H) ----------------
__global__ void out_kernel(const float* __restrict__ xin, float* __restrict__ out) {
    int idx = blockIdx.x * blockDim.x + threadIdx.x;   // float4 elements
    if (idx >= TT*BB*HH/4) return;
    int k4 = idx & 127;
    int t  = (idx >> 7) & 255;
    int b  = idx >> 15;
    float4 v = *(const float4*)(xin + ((size_t)t*BB + b)*HH + k4*4);
    *(float4*)(out + (size_t)idx*4) = v;
}

// ---------------- launch ----------------
extern "C" void kernel_launch(void* const* d_in, const int* in_sizes, int n_in,
                              void* d_out, int out_size)
{
    const float* inputs = nullptr;
    const float* weight = nullptr;
    const float* biasp  = nullptr;
    const int*   len    = nullptr;
    for (int i = 0; i < n_in; i++) {
        switch (in_sizes[i]) {
            case TT*BB*HH:  inputs = (const float*)d_in[i]; break;  // 8388608
            case 11534336:  weight = (const float*)d_in[i]; break;
            case 4*G5:      biasp  = (const float*)d_in[i]; break;  // 10240
            case BB:        len    = (const int*)  d_in[i]; break;  // 64
        }
    }

    float *px, *py, *pxi, *ph0, *ph1, *pwt;
    unsigned* pbar;
    cudaGetSymbolAddress((void**)&px,  g_x);
    cudaGetSymbolAddress((void**)&py,  g_y);
    cudaGetSymbolAddress((void**)&pxi, g_xi);
    cudaGetSymbolAddress((void**)&ph0, g_h0);
    cudaGetSymbolAddress((void**)&ph1, g_h1);
    cudaGetSymbolAddress((void**)&pwt, g_wt);
    cudaGetSymbolAddress((void**)&pbar, g_bar);

    prep_kernel<<<(TT*BB*HH/4 + 255)/256, 256>>>(inputs, len);
    packw_kernel<<<(4*HH*G5 + 255)/256, 256>>>(weight);

    float* xin  = px;
    float* yout = py;
    for (int l = 0; l < 4; l++) {
        int rev = l & 1;
        gemm_xi_kernel<<<dim3(128, 24), 256>>>(
            xin, weight + (size_t)l*LAYER_W_STRIDE, pxi, len, rev);
        cudaMemsetAsync(ph0, 0, (size_t)BB*HH*sizeof(float));
        cudaMemsetAsync(pbar, 0, 2*sizeof(unsigned));
        lstm_layer_kernel<<<NCTA, 256>>>(
            pxi, pwt + (size_t)l*G5*HH, biasp + (size_t)l*G5,
            len, ph0, ph1, yout, rev);
        float* tmp = xin; xin = yout; yout = tmp;
    }
    out_kernel<<<(TT*BB*HH/4 + 255)/256, 256>>>(xin, (float*)d_out);
}

// round 5
// speedup vs baseline: 1.0043x; 1.0043x over previous
#include <cuda_runtime.h>
#include <cstdint>
#include <cstddef>

#define TT 256
#define BB 64
#define HH 512
#define G6 3072
#define G5 2560
#define LAYER_W_STRIDE (512*3072 + 512*2560)   /* 2883584 */
#define WHH_OFF (512*3072)                      /* 1572864 */
#define NCTA 128

// ---------------- device scratch (static, no runtime alloc) ----------------
__device__ float g_x [(size_t)TT*BB*HH];          // layer input  [t][b][k]
__device__ float g_y [(size_t)TT*BB*HH];          // layer output [t][b][k]
__device__ float g_xi[(size_t)TT*BB*G6];          // xi [t][b][g]
__device__ float g_h0[BB*HH];
__device__ float g_h1[BB*HH];
__device__ float g_wt[(size_t)4*G5*HH];           // W_hh packed [l][hid][gate][k]
__device__ unsigned g_bar[2];                     // [0]=count, [1]=epoch

// ---------------- f32x2 packed FMA (sm_100+) ----------------
__device__ __forceinline__ float2 ffma2(float2 a, float2 b, float2 c) {
    union U { float2 f; unsigned long long u; };
    U A, B, C, D;
    A.f = a; B.f = b; C.f = c;
    asm("fma.rn.f32x2 %0, %1, %2, %3;" : "=l"(D.u) : "l"(A.u), "l"(B.u), "l"(C.u));
    return D.f;
}

__device__ __forceinline__ float sigmoidf_(float x) {
    return 1.0f / (1.0f + __expf(-x));
}

// ---------------- prep: transpose (B,T,H)->(T,B,H) and mask ----------------
__global__ void prep_kernel(const float* __restrict__ in, const int* __restrict__ len) {
    int idx = blockIdx.x * blockDim.x + threadIdx.x;   // float4 elements
    if (idx >= TT*BB*HH/4) return;
    int k4 = idx & 127;
    int b  = (idx >> 7) & 63;
    int t  = idx >> 13;
    float4 v = make_float4(0.f, 0.f, 0.f, 0.f);
    if (t < len[b])
        v = *(const float4*)(in + (size_t)(b*TT + t)*HH + k4*4);
    *(float4*)(g_x + (size_t)idx*4) = v;
}

// ---------------- pack W_hh[k][g*512+hid] -> wt[l][(hid*5+g)][k] ----------------
__global__ void packw_kernel(const float* __restrict__ weight) {
    int idx = blockIdx.x * blockDim.x + threadIdx.x;
    if (idx >= 4*HH*G5) return;
    int col = idx % G5;
    int k   = (idx / G5) % HH;
    int l   = idx / (G5*HH);
    int hid = col & 511, g = col >> 9;
    float v = weight[(size_t)l*LAYER_W_STRIDE + WHH_OFF + (size_t)k*G5 + col];
    g_wt[(size_t)l*(G5*HH) + (size_t)((hid*5 + g) << 9) + k] = v;
}

// ---------------- xi GEMM: (16384x512)x(512x3072), gathered A rows ----------------
__global__ __launch_bounds__(256, 2)
void gemm_xi_kernel(const float* __restrict__ X, const float* __restrict__ W,
                    float* __restrict__ XI, const int* __restrict__ len, int rev)
{
    __shared__ float As[8][128];
    __shared__ float Bs[8][128];
    __shared__ int   srow[128];
    int tid = threadIdx.x;
    int rowBase = blockIdx.x * 128;
    int colBase = blockIdx.y * 128;
    if (tid < 128) {
        int r = rowBase + tid;
        int t = r >> 6, b = r & 63;
        if (rev) { int L = len[b]; t = (t < L) ? (L - 1 - t) : t; }
        srow[tid] = t*BB + b;
    }
    __syncthreads();

    float2 acc[8][4];
    #pragma unroll
    for (int i = 0; i < 8; i++)
        #pragma unroll
        for (int j = 0; j < 4; j++) acc[i][j] = make_float2(0.f, 0.f);

    int am = tid >> 1, akq = (tid & 1) * 4;
    int bk = tid >> 5, bn  = (tid & 31) * 4;
    int ty8 = (tid >> 4) * 8, tx8 = (tid & 15) * 8;

    for (int k0 = 0; k0 < 512; k0 += 8) {
        float4 av = *(const float4*)(X + (size_t)srow[am]*HH + k0 + akq);
        float4 bv = *(const float4*)(W + (size_t)(k0 + bk)*G6 + colBase + bn);
        As[akq+0][am] = av.x; As[akq+1][am] = av.y;
        As[akq+2][am] = av.z; As[akq+3][am] = av.w;
        *(float4*)&Bs[bk][bn] = bv;
        __syncthreads();
        #pragma unroll
        for (int kk = 0; kk < 8; kk++) {
            float4 a0 = *(float4*)&As[kk][ty8];
            float4 a1 = *(float4*)&As[kk][ty8+4];
            float4 b0 = *(float4*)&Bs[kk][tx8];
            float4 b1 = *(float4*)&Bs[kk][tx8+4];
            float  ar[8] = {a0.x,a0.y,a0.z,a0.w,a1.x,a1.y,a1.z,a1.w};
            float2 br[4] = {make_float2(b0.x,b0.y), make_float2(b0.z,b0.w),
                            make_float2(b1.x,b1.y), make_float2(b1.z,b1.w)};
            #pragma unroll
            for (int i = 0; i < 8; i++) {
                float2 ad = make_float2(ar[i], ar[i]);
                #pragma unroll
                for (int jp = 0; jp < 4; jp++)
                    acc[i][jp] = ffma2(ad, br[jp], acc[i][jp]);
            }
        }
        __syncthreads();
    }

    #pragma unroll
    for (int i = 0; i < 8; i++) {
        float* out = XI + (size_t)(rowBase + ty8 + i)*G6 + colBase + tx8;
        *(float4*)(out)     = make_float4(acc[i][0].x, acc[i][0].y, acc[i][1].x, acc[i][1].y);
        *(float4*)(out + 4) = make_float4(acc[i][2].x, acc[i][2].y, acc[i][3].x, acc[i][3].y);
    }
}

// ---------------- persistent per-layer recurrence ----------------
// 128 CTAs (one per SM, all co-resident) x 256 threads.
// CTA owns 4 hidden units for all 256 steps. Weights live in smem for the
// whole layer; c lives in a register; h ping-pongs through global with a
// software grid barrier between steps.
__global__ __launch_bounds__(256)
void lstm_layer_kernel(const float* __restrict__ xi_base, // [T][B][G6]
                       const float* __restrict__ wt,      // packed layer W_hh
                       const float* __restrict__ bias,    // [G5]
                       const int*   __restrict__ len,
                       float* __restrict__ hbuf0,
                       float* __restrict__ hbuf1,
                       float* __restrict__ y,
                       int rev)
{
    __shared__ float sh_w[20*512];     // 40 KB: this CTA's 20 weight rows
    __shared__ float sh_h[64*68];      // 17 KB: 64-k chunk of h, pad-68 (conflict-free)

    int tid = threadIdx.x;
    int hl = tid >> 6, b = tid & 63;
    int hid0 = blockIdx.x * 4;
    int hid  = hid0 + hl;

    // one-time loads
    const float4* wsrc = (const float4*)(wt + (size_t)hid0 * 5 * 512);
    #pragma unroll
    for (int i = tid; i < 20*512/4; i += 256)
        ((float4*)sh_w)[i] = wsrc[i];

    float bval[5];
    #pragma unroll
    for (int g = 0; g < 5; g++) bval[g] = bias[g*512 + hid];
    int L = len[b];
    float c = 0.0f;

    const float* hin = hbuf0;
    float*       hout = hbuf1;

    int sb = tid >> 2;                 // staging batch row 0..63
    int sk = (tid & 3) * 16;           // staging k offset within 64-chunk

    __syncthreads();

    for (int s = 0; s < TT; s++) {
        const float* xi = xi_base + (size_t)s * BB * G6;

        float2 acc[5];
        #pragma unroll
        for (int g = 0; g < 5; g++) acc[g] = make_float2(0.f, 0.f);

        for (int k0 = 0; k0 < 512; k0 += 64) {
            // stage h chunk (bypass L1: h is produced by other SMs)
            const float4* hsrc = (const float4*)(hin + (size_t)sb*HH + k0 + sk);
            float4 v0 = __ldcg(hsrc + 0);
            float4 v1 = __ldcg(hsrc + 1);
            float4 v2 = __ldcg(hsrc + 2);
            float4 v3 = __ldcg(hsrc + 3);
            *(float4*)&sh_h[sb*68 + sk +  0] = v0;
            *(float4*)&sh_h[sb*68 + sk +  4] = v1;
            *(float4*)&sh_h[sb*68 + sk +  8] = v2;
            *(float4*)&sh_h[sb*68 + sk + 12] = v3;
            __syncthreads();
            #pragma unroll
            for (int kk = 0; kk < 64; kk += 4) {
                float4 hv = *(float4*)&sh_h[b*68 + kk];
                float2 h01 = make_float2(hv.x, hv.y);
                float2 h23 = make_float2(hv.z, hv.w);
                #pragma unroll
                for (int g = 0; g < 5; g++) {
                    float4 wv = *(float4*)&sh_w[(hl*5 + g)*512 + k0 + kk];
                    acc[g] = ffma2(h01, make_float2(wv.x, wv.y), acc[g]);
                    acc[g] = ffma2(h23, make_float2(wv.z, wv.w), acc[g]);
                }
            }
            __syncthreads();
        }

        float gv[5];
        #pragma unroll
        for (int g = 0; g < 5; g++)
            gv[g] = acc[g].x + acc[g].y
                  + xi[(size_t)b*G6 + g*512 + hid] + bval[g];

        float ig = sigmoidf_(gv[0]);
        float fg = sigmoidf_(gv[1]);
        float gc = tanhf(gv[2]);
        float og = sigmoidf_(gv[3]);
        float rg = sigmoidf_(gv[4]);
        float lin = xi[(size_t)b*G6 + 5*512 + hid];

        float cn, hn;
        if (s < L) {
            cn = fg*c + ig*gc;
            hn = rg*(og*tanhf(cn)) + (1.f - rg)*lin;
        } else {
            cn = 0.f; hn = 0.f;
        }
        c = cn;
        hout[b*HH + hid] = hn;
        int dst = rev ? ((s < L) ? (L - 1 - s) : s) : s;
        y[((size_t)dst*BB + b)*HH + hid] = hn;

        // ---- grid barrier (sense via monotonically increasing epoch) ----
        if (s != TT-1) {
            __threadfence();
            __syncthreads();
            if (tid == 0) {
                unsigned target = (unsigned)(s + 1);
                if (atomicAdd(&g_bar[0], 1u) == NCTA - 1) {
                    atomicExch(&g_bar[0], 0u);
                    __threadfence();
                    atomicAdd(&g_bar[1], 1u);
                }
                unsigned v;
                for (;;) {
                    asm volatile("ld.acquire.gpu.u32 %0, [%1];"
                                 : "=r"(v) : "l"(&g_bar[1]));
                    if (v >= target) break;
                    __nanosleep(64);
                }
            }
            __syncthreads();
        }

        // swap h buffers
        const float* tmp = hin; hin = hout; hout = (float*)tmp;
    }
}

// ---------------- final transpose (T,B,H)->(B,T,H) ----------------
__global__ void out_kernel(const float* __restrict__ xin, float* __restrict__ out) {
    int idx = blockIdx.x * blockDim.x + threadIdx.x;   // float4 elements
    if (idx >= TT*BB*HH/4) return;
    int k4 = idx & 127;
    int t  = (idx >> 7) & 255;
    int b  = idx >> 15;
    float4 v = *(const float4*)(xin + ((size_t)t*BB + b)*HH + k4*4);
    *(float4*)(out + (size_t)idx*4) = v;
}

// ---------------- launch ----------------
extern "C" void kernel_launch(void* const* d_in, const int* in_sizes, int n_in,
                              void* d_out, int out_size)
{
    const float* inputs = nullptr;
    const float* weight = nullptr;
    const float* biasp  = nullptr;
    const int*   len    = nullptr;
    for (int i = 0; i < n_in; i++) {
        switch (in_sizes[i]) {
            case TT*BB*HH:  inputs = (const float*)d_in[i]; break;  // 8388608
            case 11534336:  weight = (const float*)d_in[i]; break;
            case 4*G5:      biasp  = (const float*)d_in[i]; break;  // 10240
            case BB:        len    = (const int*)  d_in[i]; break;  // 64
        }
    }

    float *px, *py, *pxi, *ph0, *ph1, *pwt;
    unsigned* pbar;
    cudaGetSymbolAddress((void**)&px,  g_x);
    cudaGetSymbolAddress((void**)&py,  g_y);
    cudaGetSymbolAddress((void**)&pxi, g_xi);
    cudaGetSymbolAddress((void**)&ph0, g_h0);
    cudaGetSymbolAddress((void**)&ph1, g_h1);
    cudaGetSymbolAddress((void**)&pwt, g_wt);
    cudaGetSymbolAddress((void**)&pbar, g_bar);

    prep_kernel<<<(TT*BB*HH/4 + 255)/256, 256>>>(inputs, len);
    packw_kernel<<<(4*HH*G5 + 255)/256, 256>>>(weight);

    float* xin  = px;
    float* yout = py;
    for (int l = 0; l < 4; l++) {
        int rev = l & 1;
        gemm_xi_kernel<<<dim3(128, 24), 256>>>(
            xin, weight + (size_t)l*LAYER_W_STRIDE, pxi, len, rev);
        cudaMemsetAsync(ph0, 0, (size_t)BB*HH*sizeof(float));
        cudaMemsetAsync(pbar, 0, 2*sizeof(unsigned));
        lstm_layer_kernel<<<NCTA, 256>>>(
            pxi, pwt + (size_t)l*G5*HH, biasp + (size_t)l*G5,
            len, ph0, ph1, yout, rev);
        float* tmp = xin; xin = yout; yout = tmp;
    }
    out_kernel<<<(TT*BB*HH/4 + 255)/256, 256>>>(xin, (float*)d_out);
}

// round 7
// speedup vs baseline: 1.8016x; 1.7938x over previous
#include <cuda_runtime.h>
#include <cstdint>
#include <cstddef>

#define TT 256
#define BB 64
#define HH 512
#define G6 3072
#define G5 2560
#define LAYER_W_STRIDE (512*3072 + 512*2560)   /* 2883584 */
#define WHH_OFF (512*3072)                      /* 1572864 */
#define NCTA 128

// smem layout for lstm kernel (floats)
#define OFF_W 0            /* 4*5*512   = 10240 floats (40KB)  */
#define OFF_H 10240        /* 512*64    = 32768 floats (128KB) */
#define OFF_R 43008        /* 8*32*42   = 10752 floats (42KB)  */
#define SMEM_LSTM ((10240 + 32768 + 10752) * 4)   /* 215040 B */

// ---------------- device scratch (static, no runtime alloc) ----------------
__device__ float g_xt[(size_t)TT*HH*BB];          // layer input  [t][k][b]
__device__ float g_yt[(size_t)TT*HH*BB];          // layer output [t][k][b]
__device__ float g_xr[(size_t)TT*HH*BB];          // reversed input
__device__ float g_xi[(size_t)TT*G6*BB];          // xi [t][g][b]
__device__ float g_h0[HH*BB];                     // h [k][b]
__device__ float g_h1[HH*BB];
__device__ float g_wt[(size_t)4*G5*HH];           // W_hh packed [l][hid*5+g][k]
__device__ unsigned g_bar[2];                     // [0]=count, [1]=epoch

// ---------------- f32x2 packed FMA (sm_100+) ----------------
__device__ __forceinline__ float2 ffma2(float2 a, float2 b, float2 c) {
    union U { float2 f; unsigned long long u; };
    U A, B, C, D;
    A.f = a; B.f = b; C.f = c;
    asm("fma.rn.f32x2 %0, %1, %2, %3;" : "=l"(D.u) : "l"(A.u), "l"(B.u), "l"(C.u));
    return D.f;
}

__device__ __forceinline__ float sigmoidf_(float x) {
    return 1.0f / (1.0f + __expf(-x));
}

// ---------------- prep: (B,T,K) -> [t][k][b], masked ----------------
__global__ void prep_kernel(const float* __restrict__ in, const int* __restrict__ len) {
    int idx = blockIdx.x * blockDim.x + threadIdx.x;
    if (idx >= TT*HH*BB) return;
    int b = idx & 63;
    int k = (idx >> 6) & 511;
    int t = idx >> 15;
    float v = 0.f;
    if (t < len[b]) v = in[((size_t)b*TT + t)*HH + k];
    g_xt[idx] = v;
}

// ---------------- reverse gather: xr[t][k][b] = xt[t'][k][b] ----------------
__global__ void reverse_kernel(const float* __restrict__ xt, float* __restrict__ xr,
                               const int* __restrict__ len) {
    int idx = blockIdx.x * blockDim.x + threadIdx.x;
    if (idx >= TT*HH*BB) return;
    int b = idx & 63;
    int k = (idx >> 6) & 511;
    int t = idx >> 15;
    int L = len[b];
    int tp = (t < L) ? (L - 1 - t) : t;
    xr[idx] = xt[((size_t)tp*HH + k)*BB + b];
}

// ---------------- pack W_hh[k][g*512+hid] -> wt[l][(hid*5+g)][k] ----------------
__global__ void packw_kernel(const float* __restrict__ weight) {
    int idx = blockIdx.x * blockDim.x + threadIdx.x;
    if (idx >= 4*HH*G5) return;
    int col = idx % G5;
    int k   = (idx / G5) % HH;
    int l   = idx / (G5*HH);
    int hid = col & 511, g = col >> 9;
    float v = weight[(size_t)l*LAYER_W_STRIDE + WHH_OFF + (size_t)k*G5 + col];
    g_wt[(size_t)l*(G5*HH) + (size_t)((hid*5 + g) << 9) + k] = v;
}

// ---------------- xi GEMM: xi[t][g][b] = sum_k W[k][g] * X[t][k][b] ----------------
// tiles: 128 g x 128 m (m = t*64+b). B-tile skewed to kill LDS conflicts.
__device__ __forceinline__ int bskew(int c) { return c + ((c >> 5) << 2); }

__global__ __launch_bounds__(256, 2)
void gemm_xi_kernel(const float* __restrict__ X, const float* __restrict__ W,
                    float* __restrict__ XI)
{
    __shared__ float As[8][128];
    __shared__ float Bs[8][144];    // skewed width: bskew(124)+3 = 139 < 144
    int tid = threadIdx.x;
    int mBase = blockIdx.x * 128;
    int gBase = blockIdx.y * 128;

    float2 acc[8][4];
    #pragma unroll
    for (int i = 0; i < 8; i++)
        #pragma unroll
        for (int j = 0; j < 4; j++) acc[i][j] = make_float2(0.f, 0.f);

    int sk  = tid >> 5;             // 0..7 staging k row
    int sc4 = (tid & 31) * 4;       // staging col (x4)
    int ty8 = (tid >> 4) * 8;       // g rows
    int tx8 = (tid & 15) * 8;       // m cols

    int m4 = mBase + sc4;
    const float* bsrc = X + ((size_t)(m4 >> 6) * HH) * BB + (m4 & 63);
    const float* asrc = W + gBase + sc4;
    int bsw = bskew(sc4);
    int c0 = bskew(tx8), c1 = bskew(tx8 + 4);

    for (int k0 = 0; k0 < 512; k0 += 8) {
        float4 av = *(const float4*)(asrc + (size_t)(k0 + sk)*G6);
        float4 bv = *(const float4*)(bsrc + (size_t)(k0 + sk)*BB);
        *(float4*)&As[sk][sc4] = av;
        *(float4*)&Bs[sk][bsw] = bv;
        __syncthreads();
        #pragma unroll
        for (int kk = 0; kk < 8; kk++) {
            float4 a0 = *(float4*)&As[kk][ty8];
            float4 a1 = *(float4*)&As[kk][ty8+4];
            float4 b0 = *(float4*)&Bs[kk][c0];
            float4 b1 = *(float4*)&Bs[kk][c1];
            float  ar[8] = {a0.x,a0.y,a0.z,a0.w,a1.x,a1.y,a1.z,a1.w};
            float2 br[4] = {make_float2(b0.x,b0.y), make_float2(b0.z,b0.w),
                            make_float2(b1.x,b1.y), make_float2(b1.z,b1.w)};
            #pragma unroll
            for (int i = 0; i < 8; i++) {
                float2 ad = make_float2(ar[i], ar[i]);
                #pragma unroll
                for (int jp = 0; jp < 4; jp++)
                    acc[i][jp] = ffma2(ad, br[jp], acc[i][jp]);
            }
        }
        __syncthreads();
    }

    int m0 = mBase + tx8;
    int t  = m0 >> 6;
    int b0 = m0 & 63;
    #pragma unroll
    for (int i = 0; i < 8; i++) {
        float* o = XI + ((size_t)t*G6 + gBase + ty8 + i)*BB + b0;
        *(float4*)(o)     = make_float4(acc[i][0].x, acc[i][0].y, acc[i][1].x, acc[i][1].y);
        *(float4*)(o + 4) = make_float4(acc[i][2].x, acc[i][2].y, acc[i][3].x, acc[i][3].y);
    }
}

// ---------------- persistent per-layer recurrence ----------------
// 128 CTAs x 256 thr; CTA owns 4 hids. Whole h (128KB) staged to smem per
// step via linear copy; FMA phase: thread=(kh 0..7, bp 0..31) packs f32x2
// over batch; partials reduced via smem; output phase: thread=(hl, b).
__global__ __launch_bounds__(256)
void lstm_layer_kernel(const float* __restrict__ xi_base, // [T][G6][B]
                       const float* __restrict__ wt,      // packed layer W_hh
                       const float* __restrict__ bias,    // [G5]
                       const int*   __restrict__ len,
                       float* __restrict__ hbuf0,
                       float* __restrict__ hbuf1,
                       float* __restrict__ y,             // [T][H][B]
                       int rev)
{
    extern __shared__ float smf[];
    int tid = threadIdx.x;
    int hid0 = blockIdx.x * 4;

    // FMA-phase mapping
    int kh = tid >> 5;          // k-slice 0..7 (64 k each)
    int bp = tid & 31;          // batch pair 0..31
    // output-phase mapping
    int hl_o = tid >> 6;        // 0..3
    int b_o  = tid & 63;
    int hid_o = hid0 + hl_o;

    // one-time: weights -> smem (40KB linear)
    {
        const float4* ws = (const float4*)(wt + (size_t)hid0 * 5 * 512);
        float4* wd = (float4*)(smf + OFF_W);
        #pragma unroll
        for (int i = 0; i < 10; i++) wd[tid + i*256] = ws[tid + i*256];
    }
    float bval[5];
    #pragma unroll
    for (int g = 0; g < 5; g++) bval[g] = bias[g*512 + hid_o];
    int L = len[b_o];
    float c = 0.0f;

    const float* hin  = hbuf0;
    float*       hout = hbuf1;
    __syncthreads();

    for (int s = 0; s < TT; s++) {
        // xi prefetch (output mapping) — coalesced
        const float* xs = xi_base + (size_t)s*G6*BB;
        float xiv[6];
        #pragma unroll
        for (int g = 0; g < 6; g++)
            xiv[g] = __ldcs(xs + (size_t)(g*512 + hid_o)*BB + b_o);

        // stage whole h: 128KB linear copy, MLP=32
        {
            const float4* hs = (const float4*)hin;
            float4* hd = (float4*)(smf + OFF_H);
            #pragma unroll
            for (int i = 0; i < 32; i++) {
                int idx = tid + i*256;
                hd[idx] = __ldcg(hs + idx);
            }
        }
        __syncthreads();

        // FMA phase: acc[q] (q = hl*5+g), f32x2 over batch pair bp
        float2 acc[20];
        #pragma unroll
        for (int q = 0; q < 20; q++) acc[q] = make_float2(0.f, 0.f);

        const float* shh = smf + OFF_H + 2*bp;
        const float* shw = smf + OFF_W + kh*64;
        #pragma unroll 2
        for (int k4 = 0; k4 < 64; k4 += 4) {
            int kb = (kh*64 + k4) * 64;
            float2 hv0 = *(const float2*)(shh + kb);
            float2 hv1 = *(const float2*)(shh + kb + 64);
            float2 hv2 = *(const float2*)(shh + kb + 128);
            float2 hv3 = *(const float2*)(shh + kb + 192);
            #pragma unroll
            for (int q = 0; q < 20; q++) {
                float4 w4 = *(const float4*)(shw + q*512 + k4);
                acc[q] = ffma2(hv0, make_float2(w4.x, w4.x), acc[q]);
                acc[q] = ffma2(hv1, make_float2(w4.y, w4.y), acc[q]);
                acc[q] = ffma2(hv2, make_float2(w4.z, w4.z), acc[q]);
                acc[q] = ffma2(hv3, make_float2(w4.w, w4.w), acc[q]);
            }
        }

        // write partials (stride 42 avoids read conflicts)
        {
            float* rb = smf + OFF_R + (kh*32 + bp)*42;
            #pragma unroll
            for (int q = 0; q < 20; q++) *(float2*)(rb + 2*q) = acc[q];
        }
        __syncthreads();

        // reduce + gates (output mapping)
        float gv[5];
        #pragma unroll
        for (int g = 0; g < 5; g++) gv[g] = xiv[g] + bval[g];
        {
            const float* rbase = smf + OFF_R + (b_o >> 1)*42 + (b_o & 1);
            #pragma unroll
            for (int kh2 = 0; kh2 < 8; kh2++) {
                const float* p = rbase + kh2*32*42;
                #pragma unroll
                for (int g = 0; g < 5; g++)
                    gv[g] += p[(hl_o*5 + g)*2];
            }
        }

        float ig = sigmoidf_(gv[0]);
        float fg = sigmoidf_(gv[1]);
        float gc = tanhf(gv[2]);
        float og = sigmoidf_(gv[3]);
        float rg = sigmoidf_(gv[4]);
        float lin = xiv[5];

        float cn, hn;
        if (s < L) {
            cn = fg*c + ig*gc;
            hn = rg*(og*tanhf(cn)) + (1.f - rg)*lin;
        } else {
            cn = 0.f; hn = 0.f;
        }
        c = cn;
        hout[hid_o*BB + b_o] = hn;                       // [k][b] coalesced
        int dst = rev ? ((s < L) ? (L - 1 - s) : s) : s;
        y[((size_t)dst*HH + hid_o)*BB + b_o] = hn;       // coalesced

        // ---- grid barrier ----
        if (s != TT-1) {
            __threadfence();
            __syncthreads();
            if (tid == 0) {
                unsigned target = (unsigned)(s + 1);
                if (atomicAdd(&g_bar[0], 1u) == NCTA - 1) {
                    atomicExch(&g_bar[0], 0u);
                    __threadfence();
                    atomicAdd(&g_bar[1], 1u);
                }
                unsigned v;
                for (;;) {
                    asm volatile("ld.acquire.gpu.u32 %0, [%1];"
                                 : "=r"(v) : "l"(&g_bar[1]));
                    if (v >= target) break;
                    __nanosleep(64);
                }
            }
            __syncthreads();
        }
        const float* tmp = hin; hin = hout; hout = (float*)tmp;
    }
}

// ---------------- final: [t][k][b] -> (B,T,K) ----------------
__global__ void out_kernel(const float* __restrict__ xt, float* __restrict__ out) {
    int idx = blockIdx.x * blockDim.x + threadIdx.x;
    if (idx >= TT*HH*BB) return;
    int k = idx & 511;
    int t = (idx >> 9) & 255;
    int b = idx >> 17;
    out[idx] = xt[((size_t)t*HH + k)*BB + b];
}

// ---------------- launch ----------------
extern "C" void kernel_launch(void* const* d_in, const int* in_sizes, int n_in,
                              void* d_out, int out_size)
{
    const float* inputs = nullptr;
    const float* weight = nullptr;
    const float* biasp  = nullptr;
    const int*   len    = nullptr;
    for (int i = 0; i < n_in; i++) {
        switch (in_sizes[i]) {
            case TT*BB*HH:  inputs = (const float*)d_in[i]; break;  // 8388608
            case 11534336:  weight = (const float*)d_in[i]; break;
            case 4*G5:      biasp  = (const float*)d_in[i]; break;  // 10240
            case BB:        len    = (const int*)  d_in[i]; break;  // 64
        }
    }

    float *pxt, *pyt, *pxr, *pxi, *ph0, *ph1, *pwt;
    unsigned* pbar;
    cudaGetSymbolAddress((void**)&pxt, g_xt);
    cudaGetSymbolAddress((void**)&pyt, g_yt);
    cudaGetSymbolAddress((void**)&pxr, g_xr);
    cudaGetSymbolAddress((void**)&pxi, g_xi);
    cudaGetSymbolAddress((void**)&ph0, g_h0);
    cudaGetSymbolAddress((void**)&ph1, g_h1);
    cudaGetSymbolAddress((void**)&pwt, g_wt);
    cudaGetSymbolAddress((void**)&pbar, g_bar);

    cudaFuncSetAttribute(lstm_layer_kernel,
                         cudaFuncAttributeMaxDynamicSharedMemorySize, SMEM_LSTM);

    prep_kernel<<<(TT*HH*BB + 255)/256, 256>>>(inputs, len);
    packw_kernel<<<(4*HH*G5 + 255)/256, 256>>>(weight);

    float* xin  = pxt;
    float* yout = pyt;
    for (int l = 0; l < 4; l++) {
        int rev = l & 1;
        const float* gsrc = xin;
        if (rev) {
            reverse_kernel<<<(TT*HH*BB + 255)/256, 256>>>(xin, pxr, len);
            gsrc = pxr;
        }
        gemm_xi_kernel<<<dim3(128, 24), 256>>>(
            gsrc, weight + (size_t)l*LAYER_W_STRIDE, pxi);
        cudaMemsetAsync(ph0, 0, (size_t)HH*BB*sizeof(float));
        cudaMemsetAsync(pbar, 0, 2*sizeof(unsigned));
        lstm_layer_kernel<<<NCTA, 256, SMEM_LSTM>>>(
            pxi, pwt + (size_t)l*G5*HH, biasp + (size_t)l*G5,
            len, ph0, ph1, yout, rev);
        float* tmp = xin; xin = yout; yout = tmp;
    }
    out_kernel<<<(TT*HH*BB + 255)/256, 256>>>(xin, (float*)d_out);
}